// round 12
// baseline (speedup 1.0000x reference)
#include <cuda_runtime.h>
#include <math.h>

#define KTOT  2304          // 9*256, k = (ky*3+kx)*256 + c  (chain order)
#define NANCH 76725
#define MAXDET 300
#define NMSCAP 8192

#define BK 16
#define NT  144             // KTOT/BK
#define BUFSZP 2346240      // sum over levels of (H+2)^2 * 256

#define HID_ELEM (2304*256)       // per-layer weight elems
#define OUT_ELEM (2304*64)

// ---------------- scratch (device globals; no allocation) ----------------
__device__ __align__(16) float  g_feat[BUFSZP];
__device__ __align__(16) float  g_hA0[BUFSZP];
__device__ __align__(16) float  g_hA1[BUFSZP];
__device__ __align__(16) float  g_hB0[BUFSZP];
__device__ __align__(16) float  g_hB1[BUFSZP];
__device__ __align__(16) float  g_wc[4 * HID_ELEM];   // cls hidden, [layer][k][m=256]
__device__ __align__(16) float  g_wr[4 * HID_ELEM];   // reg hidden, [layer][k][m=256]
__device__ __align__(16) float  g_wo_c[OUT_ELEM];     // cls out, [k][m=64] zero-padded (M=9)
__device__ __align__(16) float  g_wo_r[OUT_ELEM];     // reg out, [k][m=64] zero-padded (M=36)
__device__ float  g_scores[NANCH];
__device__ float4 g_boxes[NANCH];
__device__ float  g_cs[NANCH];     // fallback only
__device__ float4 g_cb[NANCH];
__device__ float  g_carea[NANCH];

// per-level tables (padded layout)
__constant__ int c_H[5]   = {80, 40, 20, 10, 5};
__constant__ int c_HP[5]  = {82, 42, 22, 12, 7};
__constant__ int c_PP[5]  = {6724, 1764, 484, 144, 49};
__constant__ int c_PbP[5] = {0, 1721344, 2172928, 2296832, 2333696};
__constant__ int c_str[5] = {8, 16, 32, 64, 128};
__constant__ int c_ao[5]  = {0, 57600, 72000, 75600, 76500};

// ---------------- prep: gather features into padded layout + zero halos ----------------
__global__ void prep_kernel(const float* __restrict__ f0, const float* __restrict__ f1,
                            const float* __restrict__ f2, const float* __restrict__ f3,
                            const float* __restrict__ f4)
{
    const int gid = blockIdx.x * 256 + threadIdx.x;
    if (gid >= BUFSZP) return;
    int l;
    if      (gid < 1721344) l = 0;
    else if (gid < 2172928) l = 1;
    else if (gid < 2296832) l = 2;
    else if (gid < 2333696) l = 3;
    else                    l = 4;
    const int base = c_PbP[l];
    const int PP = c_PP[l], HP = c_HP[l], H = c_H[l];
    const int rem = gid - base;
    const int c = rem / PP;
    const int q = rem - c * PP;
    const int qy = q / HP;
    const int qx = q - qy * HP;
    if (qy == 0 || qy == HP - 1 || qx == 0 || qx == HP - 1) {
        g_feat[gid] = 0.f; g_hA0[gid] = 0.f; g_hA1[gid] = 0.f;
        g_hB0[gid] = 0.f; g_hB1[gid] = 0.f;
    } else {
        const float* src = (l == 0) ? f0 : (l == 1) ? f1 : (l == 2) ? f2 : (l == 3) ? f3 : f4;
        g_feat[gid] = src[(size_t)c * H * H + (qy - 1) * H + (qx - 1)];
    }
}

// ---------------- tiled weight transpose: OIHW (m, c*9+rs) -> [k][m], coalesced ----------------
__global__ void transpose_w(const float* __restrict__ cw, const float* __restrict__ rw,
                            const float* __restrict__ cow, const float* __restrict__ row_)
{
    __shared__ float sm[32][289];
    const int b = blockIdx.x, tid = threadIdx.x;
    const float* src; float* dst; int m0, c0, Mv, DST;
    if (b < 512) {
        int sub = b >> 6;                 // head*4 + layer
        int t = b & 63;
        int head = sub >> 2, layer = sub & 3;
        m0 = (t >> 3) * 32; c0 = (t & 7) * 32;
        src = (head ? rw : cw) + (size_t)layer * HID_ELEM;
        dst = (head ? g_wr : g_wc) + (size_t)layer * HID_ELEM;
        Mv = 256; DST = 256;
    } else {
        int b2 = b - 512;
        int head = b2 >> 4;
        int t = b2 & 15;
        m0 = (t >> 3) * 32; c0 = (t & 7) * 32;
        src = head ? row_ : cow;
        dst = head ? g_wo_r : g_wo_c;
        Mv = head ? 36 : 9; DST = 64;
    }
    const int i = tid >> 3, ln = tid & 7;
    const bool vrow = (m0 + i) < Mv;
    const float* srow = src + (size_t)(m0 + i) * KTOT + c0 * 9;
#pragma unroll
    for (int w = 0; w < 36; w++) {
        int cc = w * 8 + ln;
        sm[i][cc] = vrow ? srow[cc] : 0.f;
    }
    __syncthreads();
#pragma unroll
    for (int w = 0; w < 36; w++) {
        int flat = w * 256 + tid;
        int kk = flat >> 5, ii = flat & 31;
        int rs = kk >> 5, j = kk & 31;
        dst[(size_t)(rs * 256 + c0 + j) * DST + m0 + ii] = sm[ii][j * 9 + rs];
    }
}

// ---------------- fused implicit-GEMM conv, 3-stage cp.async pipeline, halo-padded ----------------
// Serial FMA chain per output (kt, kk ascending, single accumulator) — DO NOT REORDER.
template <int OUTMODE, int MI>
__global__ __launch_bounds__(256, 2)
void conv_fused(const float* __restrict__ inC, const float* __restrict__ inR,
                const float* __restrict__ Wc,  const float* __restrict__ Wr,
                const float* __restrict__ bc,  const float* __restrict__ br,
                float* outC, float* outR)
{
    constexpr int BMv = 16 * MI;
    constexpr int BN = 128;
    constexpr int MST = OUTMODE ? 64 : 256;

    const int bx = blockIdx.x;
    int l, ts;
    if      (bx < 50) { l = 0; ts = 0;  }
    else if (bx < 63) { l = 1; ts = 50; }
    else if (bx < 67) { l = 2; ts = 63; }
    else if (bx < 68) { l = 3; ts = 67; }
    else              { l = 4; ts = 68; }
    const int H  = c_H[l];
    const int HP = c_HP[l];
    const int PP = c_PP[l];
    const int P  = H * H;
    const int base = c_PbP[l];
    const int n0 = (bx - ts) * BN;
    const int z  = blockIdx.z;

    const float* in   = (z ? inR : inC) + base;
    const float* Wt   =  z ? Wr : Wc;
    const float* bias =  z ? br : bc;
    const int    m0   = blockIdx.y * BMv;

    const int tid = threadIdx.x;
    const int tx = tid & 15, ty = tid >> 4;
    const int lane16 = tid & 15;
    const int kr     = tid >> 4;
    const int mcolA  = lane16 * MI;

    __shared__ float As[3][BK][BMv];
    __shared__ float Bs[3][BK][BN];

    float acc[MI][8];
#pragma unroll
    for (int i = 0; i < MI; i++)
#pragma unroll
        for (int j = 0; j < 8; j++) acc[i][j] = 0.f;

    // padded interior index per B column (in-bounds dummy for tail lanes)
    int pidx[8];
#pragma unroll
    for (int j = 0; j < 8; j++) {
        int p = n0 + lane16 + j * 16;
        if (p < P) {
            int py = p / H, px = p - py * H;
            pidx[j] = (py + 1) * HP + px + 1;
        } else {
            pidx[j] = HP + 1;   // any interior cell; value never used
        }
    }

    auto issue_tile = [&](int ktp, int buf) {
        const float* srcA = Wt + (size_t)(ktp * BK + kr) * MST + m0 + mcolA;
        unsigned dA = (unsigned)__cvta_generic_to_shared(&As[buf][kr][mcolA]);
#pragma unroll
        for (int q = 0; q < MI / 4; q++)
            asm volatile("cp.async.cg.shared.global [%0],[%1],16;\n"
                         :: "r"(dA + q * 16), "l"(srcA + q * 4));
        const int rs = ktp >> 4;
        const int c  = ((ktp & 15) << 4) + kr;
        const int ddo = (rs / 3 - 1) * HP + (rs - 3 * (rs / 3) - 1);
        const float* cptr = in + (size_t)c * PP + ddo;
#pragma unroll
        for (int j = 0; j < 8; j++) {
            const float* s = cptr + pidx[j];
            unsigned dB = (unsigned)__cvta_generic_to_shared(&Bs[buf][kr][lane16 + j * 16]);
            asm volatile("cp.async.ca.shared.global [%0],[%1],4;\n"
                         :: "r"(dB), "l"(s));
        }
        asm volatile("cp.async.commit_group;\n");
    };

    issue_tile(0, 0);
    issue_tile(1, 1);

    int cur = 0;
    for (int kt = 0; kt < NT; kt++) {
        asm volatile("cp.async.wait_group 1;\n");
        __syncthreads();

#pragma unroll
        for (int kk = 0; kk < BK; kk++) {
            float a[MI], b[8];
#pragma unroll
            for (int q = 0; q < MI / 4; q++)
                *(float4*)&a[4 * q] = *(const float4*)&As[cur][kk][ty * MI + 4 * q];
            *(float4*)&b[0] = *(const float4*)&Bs[cur][kk][tx * 8];
            *(float4*)&b[4] = *(const float4*)&Bs[cur][kk][tx * 8 + 4];
#pragma unroll
            for (int i = 0; i < MI; i++)
#pragma unroll
                for (int j = 0; j < 8; j++)
                    acc[i][j] = __fmaf_rn(a[i], b[j], acc[i][j]);
        }

        if (kt + 2 < NT) {
            int ib = cur + 2; if (ib >= 3) ib -= 3;
            issue_tile(kt + 2, ib);
        } else {
            asm volatile("cp.async.commit_group;\n");
        }
        cur = (cur == 2) ? 0 : cur + 1;
    }

    // ---------------- epilogues (bit-identical math) ----------------
    if (OUTMODE == 0) {
        float* out = (z ? outR : outC) + base;
#pragma unroll
        for (int j = 0; j < 8; j++) {
            int p = n0 + tx * 8 + j;
            if (p < P) {
                int yy = p / H, xx = p - yy * H;
                int paddr = (yy + 1) * HP + xx + 1;
#pragma unroll
                for (int i = 0; i < MI; i++) {
                    const int m = m0 + ty * MI + i;
                    out[(size_t)m * PP + paddr] = fmaxf(__fadd_rn(acc[i][j], bias[m]), 0.f);
                }
            }
        }
    } else if (z == 0) {  // cls out: sigmoid via double
        const int aoff = c_ao[l];
#pragma unroll
        for (int i = 0; i < MI; i++) {
            const int m = ty * MI + i;
            if (m < 9) {
                const float bsum = bias[m];
#pragma unroll
                for (int j = 0; j < 8; j++) {
                    int p = n0 + tx * 8 + j;
                    if (p < P) {
                        float logit = __fadd_rn(acc[i][j], bsum);
                        double s = 1.0 / (1.0 + exp(-(double)logit));
                        g_scores[aoff + p * 9 + m] = (float)s;
                    }
                }
            }
        }
    } else {  // reg out + anchor decode
        const int aoff = c_ao[l];
        const int stride = c_str[l];
#pragma unroll
        for (int i = 0; i < MI; i += 4) {
            const int m = ty * MI + i;
            if (m + 3 < 36) {
                const int a = m >> 2;
                const int ri = a / 3, si = a - 3 * ri;
                const double ratio = (ri == 0) ? 0.5 : ((ri == 1) ? 1.0 : 2.0);
                const double scl   = (si == 0) ? 1.0 : exp2((double)si / 3.0);
                const double bsz   = (double)(stride * 4) * scl;
                const double wA    = sqrt((bsz * bsz) / ratio);
                const double hA    = wA * ratio;
                const float b0v = bias[m + 0], b1v = bias[m + 1];
                const float b2v = bias[m + 2], b3v = bias[m + 3];
#pragma unroll
                for (int j = 0; j < 8; j++) {
                    int p = n0 + tx * 8 + j;
                    if (p < P) {
                        int yy = p / H;
                        int xx = p - yy * H;
                        double cxd = ((double)xx + 0.5) * (double)stride;
                        double cyd = ((double)yy + 0.5) * (double)stride;
                        float ax1 = (float)(cxd - 0.5 * wA);
                        float ay1 = (float)(cyd - 0.5 * hA);
                        float ax2 = (float)(cxd + 0.5 * wA);
                        float ay2 = (float)(cyd + 0.5 * hA);
                        float aw = __fsub_rn(ax2, ax1), ah = __fsub_rn(ay2, ay1);
                        float acx = __fadd_rn(ax1, 0.5f * aw);
                        float acy = __fadd_rn(ay1, 0.5f * ah);
                        float t0 = __fadd_rn(acc[i + 0][j], b0v);
                        float t1 = __fadd_rn(acc[i + 1][j], b1v);
                        float t2 = __fadd_rn(acc[i + 2][j], b2v);
                        float t3 = __fadd_rn(acc[i + 3][j], b3v);
                        float pcx = __fadd_rn(acx, __fmul_rn(__fmul_rn(t0, 0.1f), aw));
                        float pcy = __fadd_rn(acy, __fmul_rn(__fmul_rn(t1, 0.1f), ah));
                        float pw  = __fmul_rn((float)exp((double)__fmul_rn(t2, 0.2f)), aw);
                        float ph  = __fmul_rn((float)exp((double)__fmul_rn(t3, 0.2f)), ah);
                        float x1 = __fsub_rn(pcx, 0.5f * pw), y1 = __fsub_rn(pcy, 0.5f * ph);
                        float x2 = __fadd_rn(pcx, 0.5f * pw), y2 = __fadd_rn(pcy, 0.5f * ph);
                        x1 = fminf(fmaxf(x1, 0.f), 640.f);
                        y1 = fminf(fmaxf(y1, 0.f), 640.f);
                        x2 = fminf(fmaxf(x2, 0.f), 640.f);
                        y2 = fminf(fmaxf(y2, 0.f), 640.f);
                        g_boxes[aoff + p * 9 + a] = make_float4(x1, y1, x2, y2);
                    }
                }
            }
        }
    }
}

// ---------------- sort-based single-block NMS ----------------
__device__ __forceinline__ float iou_ref(float ax1, float ay1, float ax2, float ay2, float aar,
                                         float bx1, float by1, float bx2, float by2, float bar)
{
    float xx1 = fmaxf(ax1, bx1), yy1 = fmaxf(ay1, by1);
    float xx2 = fminf(ax2, bx2), yy2 = fminf(ay2, by2);
    float inter = __fmul_rn(fmaxf(__fsub_rn(xx2, xx1), 0.f),
                            fmaxf(__fsub_rn(yy2, yy1), 0.f));
    float denom = __fadd_rn(__fsub_rn(__fadd_rn(bar, aar), inter), 1e-8f);
    return __fdiv_rn(inter, denom);
}

__global__ __launch_bounds__(1024)
void nms_kernel(float* __restrict__ out)
{
    const int T = 1024;
    const int tid = threadIdx.x;

    extern __shared__ unsigned long long nms_smem[];
    unsigned long long* s_keys = nms_smem;                      // NMSCAP * 8B
    float4*             s_box  = (float4*)(nms_smem + NMSCAP);  // NMSCAP * 16B

    __shared__ int   s_hist[4096];
    __shared__ int   s_B, s_below, s_cnt, s_np, s_fp, s_fb;
    __shared__ float p_x1[MAXDET], p_y1[MAXDET], p_x2[MAXDET], p_y2[MAXDET];
    __shared__ float p_ar[MAXDET], p_sc[MAXDET];
    __shared__ int   s_mask[32];
    __shared__ float s_wv[32];
    __shared__ int   s_wi[32];

    for (int i = tid; i < 4096; i += T) s_hist[i] = 0;
    if (tid == 0) { s_cnt = 0; s_np = 0; }
    __syncthreads();

    for (int i = tid; i < NANCH; i += T) {
        float s = g_scores[i];
        if (s > 0.05f) atomicAdd(&s_hist[__float_as_uint(s) >> 18], 1);
    }
    __syncthreads();

    if (tid == 0) {
        int accum = 0, Bv = 0, below = 0;
        for (int b = 4095; b >= 0; b--) {
            int h = s_hist[b];
            if (Bv == 0) {
                if (accum + h > NMSCAP) { Bv = b + 1; below += h; }
                else accum += h;
            } else below += h;
        }
        s_B = Bv; s_below = below;
    }
    __syncthreads();
    const unsigned Bbin = (unsigned)s_B;

    for (int i = tid; i < NANCH; i += T) {
        float s = g_scores[i];
        if (s > 0.05f) {
            unsigned bits = __float_as_uint(s);
            if ((bits >> 18) >= Bbin) {
                int pos = atomicAdd(&s_cnt, 1);
                if (pos < NMSCAP)
                    s_keys[pos] = ((unsigned long long)bits << 32) | (unsigned)(~i);
            }
        }
    }
    __syncthreads();
    const int nsel = (s_cnt < NMSCAP) ? s_cnt : NMSCAP;

    if (nsel > 0) {
        int N2 = 1; while (N2 < nsel) N2 <<= 1;
        for (int i = nsel + tid; i < N2; i += T) s_keys[i] = 0ull;
        __syncthreads();

        for (int k2 = 2; k2 <= N2; k2 <<= 1) {
            for (int j = k2 >> 1; j > 0; j >>= 1) {
                for (int i = tid; i < N2; i += T) {
                    int p = i ^ j;
                    if (p > i) {
                        unsigned long long a = s_keys[i], b = s_keys[p];
                        bool dir = ((i & k2) == 0);
                        if ((a < b) == dir) { s_keys[i] = b; s_keys[p] = a; }
                    }
                }
                __syncthreads();
            }
        }

        for (int r = tid; r < nsel; r += T) {
            int idx = (int)(~(unsigned)(s_keys[r] & 0xffffffffu));
            s_box[r] = g_boxes[idx];
        }
        __syncthreads();

        for (int cur0 = 0; cur0 < nsel && s_np < MAXDET; cur0 += T) {
            int r = cur0 + tid;
            bool alive = (r < nsel);
            float4 bb = make_float4(0.f, 0.f, 0.f, 0.f);
            float ba = 0.f;
            if (alive) {
                bb = s_box[r];
                ba = __fmul_rn(__fsub_rn(bb.z, bb.x), __fsub_rn(bb.w, bb.y));
                int npc = s_np;
                for (int q = 0; q < npc; q++) {
                    float iou = iou_ref(p_x1[q], p_y1[q], p_x2[q], p_y2[q], p_ar[q],
                                        bb.x, bb.y, bb.z, bb.w, ba);
                    if (iou > 0.5f) { alive = false; break; }
                }
            }
            unsigned m = __ballot_sync(0xffffffffu, alive);
            if ((tid & 31) == 0) s_mask[tid >> 5] = (int)m;
            __syncthreads();

            while (true) {
                if (tid == 0) {
                    int fp = -1;
                    if (s_np < MAXDET) {
                        for (int wq = 0; wq < 32; wq++) {
                            unsigned mm = (unsigned)s_mask[wq];
                            if (mm) { fp = wq * 32 + __ffs(mm) - 1; break; }
                        }
                    }
                    s_fp = fp;
                }
                __syncthreads();
                int fp = s_fp;
                if (fp < 0) break;

                float4 pbb = s_box[cur0 + fp];
                float pba = __fmul_rn(__fsub_rn(pbb.z, pbb.x), __fsub_rn(pbb.w, pbb.y));
                if (tid == 0) {
                    int q = s_np;
                    p_x1[q] = pbb.x; p_y1[q] = pbb.y; p_x2[q] = pbb.z; p_y2[q] = pbb.w;
                    p_ar[q] = pba;
                    p_sc[q] = __uint_as_float((unsigned)(s_keys[cur0 + fp] >> 32));
                    s_np = q + 1;
                }
                if (alive) {
                    if (tid == fp) alive = false;
                    else {
                        float iou = iou_ref(pbb.x, pbb.y, pbb.z, pbb.w, pba,
                                            bb.x, bb.y, bb.z, bb.w, ba);
                        if (iou > 0.5f) alive = false;
                    }
                }
                unsigned m2 = __ballot_sync(0xffffffffu, alive);
                if ((tid & 31) == 0) s_mask[tid >> 5] = (int)m2;
                __syncthreads();
            }
            __syncthreads();
        }
    }

    if (tid == 0) s_fb = (s_np < MAXDET && s_below > 0) ? 1 : 0;
    __syncthreads();
    if (s_fb) {
        int npc = s_np;
        for (int i = tid; i < NANCH; i += T) {
            float s = g_scores[i];
            float v = -INFINITY;
            if (s > 0.05f && (__float_as_uint(s) >> 18) < Bbin) {
                float4 b = g_boxes[i];
                float ar = __fmul_rn(__fsub_rn(b.z, b.x), __fsub_rn(b.w, b.y));
                bool ok = true;
                for (int q = 0; q < npc; q++) {
                    float iou = iou_ref(p_x1[q], p_y1[q], p_x2[q], p_y2[q], p_ar[q],
                                        b.x, b.y, b.z, b.w, ar);
                    if (iou > 0.5f) { ok = false; break; }
                }
                if (ok) v = s;
                g_cb[i] = b; g_carea[i] = ar;
            }
            g_cs[i] = v;
        }
        __syncthreads();

        const int lane = tid & 31, w = tid >> 5;
        while (s_np < MAXDET) {
            float bv = -INFINITY; int bi = 0x7fffffff;
            for (int idx = tid; idx < NANCH; idx += T) {
                float v = g_cs[idx];
                if (v > bv || (v == bv && idx < bi)) { bv = v; bi = idx; }
            }
#pragma unroll
            for (int off = 16; off; off >>= 1) {
                float v2 = __shfl_down_sync(0xffffffffu, bv, off);
                int   i2 = __shfl_down_sync(0xffffffffu, bi, off);
                if (v2 > bv || (v2 == bv && i2 < bi)) { bv = v2; bi = i2; }
            }
            if (lane == 0) { s_wv[w] = bv; s_wi[w] = bi; }
            __syncthreads();
            if (w == 0) {
                bv = s_wv[lane]; bi = s_wi[lane];
#pragma unroll
                for (int off = 16; off; off >>= 1) {
                    float v2 = __shfl_down_sync(0xffffffffu, bv, off);
                    int   i2 = __shfl_down_sync(0xffffffffu, bi, off);
                    if (v2 > bv || (v2 == bv && i2 < bi)) { bv = v2; bi = i2; }
                }
                if (lane == 0) { s_wv[0] = bv; s_wi[0] = bi; }
            }
            __syncthreads();
            float sj = s_wv[0];
            int   j  = s_wi[0];
            if (!(sj > -INFINITY)) break;
            float4 pb = g_cb[j];
            float pba = g_carea[j];
            if (tid == 0) {
                int q = s_np;
                p_x1[q] = pb.x; p_y1[q] = pb.y; p_x2[q] = pb.z; p_y2[q] = pb.w;
                p_ar[q] = pba; p_sc[q] = sj;
                s_np = q + 1;
            }
            for (int idx = tid; idx < NANCH; idx += T) {
                float v = g_cs[idx];
                if (v == -INFINITY) continue;
                float4 b = g_cb[idx];
                float iou = iou_ref(pb.x, pb.y, pb.z, pb.w, pba,
                                    b.x, b.y, b.z, b.w, g_carea[idx]);
                if (iou > 0.5f) g_cs[idx] = -INFINITY;
            }
            __syncthreads();
        }
    }
    __syncthreads();

    const int np = s_np;
    for (int i = tid; i < MAXDET; i += T) {
        bool sel = (i < np);
        float s = sel ? p_sc[i] : 0.f;
        out[i] = s;
        out[MAXDET + i] = (s > 0.f) ? 0.f : -1.f;
        out[2 * MAXDET + 4 * i + 0] = sel ? p_x1[i] : 0.f;
        out[2 * MAXDET + 4 * i + 1] = sel ? p_y1[i] : 0.f;
        out[2 * MAXDET + 4 * i + 2] = sel ? p_x2[i] : 0.f;
        out[2 * MAXDET + 4 * i + 3] = sel ? p_y2[i] : 0.f;
    }
}

// ---------------- host launcher ----------------
extern "C" void kernel_launch(void* const* d_in, const int* in_sizes, int n_in,
                              void* d_out, int out_size)
{
    const float* f0 = (const float*)d_in[1];
    const float* f1 = (const float*)d_in[2];
    const float* f2 = (const float*)d_in[3];
    const float* f3 = (const float*)d_in[4];
    const float* f4 = (const float*)d_in[5];
    const float* cls_w  = (const float*)d_in[6];
    const float* cls_b  = (const float*)d_in[7];
    const float* cls_ow = (const float*)d_in[8];
    const float* cls_ob = (const float*)d_in[9];
    const float* reg_w  = (const float*)d_in[10];
    const float* reg_b  = (const float*)d_in[11];
    const float* reg_ow = (const float*)d_in[12];
    const float* reg_ob = (const float*)d_in[13];

    float *feat, *hA0, *hA1, *hB0, *hB1, *wc, *wr, *woc, *wor;
    cudaGetSymbolAddress((void**)&feat, g_feat);
    cudaGetSymbolAddress((void**)&hA0, g_hA0);
    cudaGetSymbolAddress((void**)&hA1, g_hA1);
    cudaGetSymbolAddress((void**)&hB0, g_hB0);
    cudaGetSymbolAddress((void**)&hB1, g_hB1);
    cudaGetSymbolAddress((void**)&wc, g_wc);
    cudaGetSymbolAddress((void**)&wr, g_wr);
    cudaGetSymbolAddress((void**)&woc, g_wo_c);
    cudaGetSymbolAddress((void**)&wor, g_wo_r);

    prep_kernel<<<(BUFSZP + 255) / 256, 256>>>(f0, f1, f2, f3, f4);
    transpose_w<<<544, 256>>>(cls_w, reg_w, cls_ow, reg_ow);

    const size_t LW = (size_t)HID_ELEM;
    dim3 gh(69, 2, 2);   // hidden: BM=128 (MI=8), 2 M-tiles, 2 heads
    dim3 go(69, 1, 2);   // out:    BM=64  (MI=4), 1 M-tile,  2 heads

    conv_fused<0, 8><<<gh, 256>>>(feat, feat, wc + 0 * LW, wr + 0 * LW,
                                  cls_b + 0,   reg_b + 0,   hA0, hB0);
    conv_fused<0, 8><<<gh, 256>>>(hA0,  hB0,  wc + 1 * LW, wr + 1 * LW,
                                  cls_b + 256, reg_b + 256, hA1, hB1);
    conv_fused<0, 8><<<gh, 256>>>(hA1,  hB1,  wc + 2 * LW, wr + 2 * LW,
                                  cls_b + 512, reg_b + 512, hA0, hB0);
    conv_fused<0, 8><<<gh, 256>>>(hA0,  hB0,  wc + 3 * LW, wr + 3 * LW,
                                  cls_b + 768, reg_b + 768, hA1, hB1);
    conv_fused<1, 4><<<go, 256>>>(hA1,  hB1,  woc, wor,
                                  cls_ob, reg_ob, nullptr, nullptr);

    const int NMS_DYN = NMSCAP * 8 + NMSCAP * 16;   // 196608 B
    cudaFuncSetAttribute(nms_kernel, cudaFuncAttributeMaxDynamicSharedMemorySize, NMS_DYN);
    nms_kernel<<<1, 1024, NMS_DYN>>>((float*)d_out);
}

// round 13
// speedup vs baseline: 1.1217x; 1.1217x over previous
#include <cuda_runtime.h>
#include <math.h>

#define KTOT  2304          // 9*256, k = (ky*3+kx)*256 + c  (chain order)
#define NANCH 76725
#define MAXDET 300
#define NMSCAP 8192

#define BK 16
#define NT  144             // KTOT/BK
#define BUFSZ (8525*256)

#define HID_ELEM (2304*256)       // per-layer weight elems
#define HID_TOT  (8*HID_ELEM)
#define OUT_ELEM (2304*64)        // combined out weights [k][64]

// ---------------- scratch (device globals; no allocation) ----------------
__device__ __align__(16) float  g_feat[BUFSZ];
__device__ __align__(16) float  g_hA0[BUFSZ];
__device__ __align__(16) float  g_hA1[BUFSZ];
__device__ __align__(16) float  g_hB0[BUFSZ];
__device__ __align__(16) float  g_hB1[BUFSZ];
__device__ __align__(16) float  g_wc[4 * HID_ELEM];   // cls hidden, [layer][k][m=256]
__device__ __align__(16) float  g_wr[4 * HID_ELEM];   // reg hidden, [layer][k][m=256]
__device__ __align__(16) float  g_wo[OUT_ELEM];       // out, [k][64]: 0-8 cls, 16-51 reg, rest 0
__device__ float  g_scores[NANCH];
__device__ float4 g_boxes[NANCH];
__device__ float  g_cs[NANCH];     // fallback only
__device__ float4 g_cb[NANCH];
__device__ float  g_carea[NANCH];

// per-level tables
__constant__ int c_H[5]   = {80, 40, 20, 10, 5};
__constant__ int c_Pb[5]  = {0, 1638400, 2048000, 2150400, 2176000};
__constant__ int c_str[5] = {8, 16, 32, 64, 128};
__constant__ int c_ao[5]  = {0, 57600, 72000, 75600, 76500};

// ---------------- weight transpose: OIHW (m, c*9+rs) -> [k][m], k = rs*256+c ----
__global__ void transpose_w(const float* __restrict__ cw, const float* __restrict__ rw,
                            const float* __restrict__ cow, const float* __restrict__ row_)
{
    const int gid = blockIdx.x * 256 + threadIdx.x;
    if (gid < HID_TOT) {
        const int sub = gid / HID_ELEM;            // head*4 + layer
        const int rem = gid - sub * HID_ELEM;
        const int k = rem >> 8, m = rem & 255;
        const int c = k & 255, rs = k >> 8;
        const int head = sub >> 2, layer = sub & 3;
        const float* src = (head ? rw : cw) + (size_t)layer * HID_ELEM + (size_t)m * KTOT + c * 9 + rs;
        float*       dst = (head ? g_wr : g_wc) + (size_t)layer * HID_ELEM + (size_t)k * 256 + m;
        *dst = *src;
    } else {
        const int r2 = gid - HID_TOT;
        if (r2 >= OUT_ELEM) return;
        const int k = r2 >> 6, col = r2 & 63;
        const int c = k & 255, rs = k >> 8;
        float v = 0.f;
        if (col < 9)                      v = cow[(size_t)col * KTOT + c * 9 + rs];
        else if (col >= 16 && col < 52)   v = row_[(size_t)(col - 16) * KTOT + c * 9 + rs];
        g_wo[r2] = v;
    }
}

// ---------------- hidden implicit-GEMM conv, 3-stage cp.async pipeline ----------------
// Serial FMA chain per output (kt, kk ascending, single accumulator) — DO NOT REORDER.
__global__ __launch_bounds__(256, 2)
void conv_hidden(const float* __restrict__ inC, const float* __restrict__ inR,
                 const float* __restrict__ Wc,  const float* __restrict__ Wr,
                 const float* __restrict__ bc,  const float* __restrict__ br,
                 float* outC, float* outR)
{
    constexpr int MI = 8;
    constexpr int BMv = 128;
    constexpr int BN = 128;
    constexpr int MST = 256;

    const int bx = blockIdx.x;
    int l, ts;
    if      (bx < 50) { l = 0; ts = 0;  }
    else if (bx < 63) { l = 1; ts = 50; }
    else if (bx < 67) { l = 2; ts = 63; }
    else if (bx < 68) { l = 3; ts = 67; }
    else              { l = 4; ts = 68; }
    const int H = c_H[l];
    const int P = H * H;
    const int base = c_Pb[l];
    const int n0 = (bx - ts) * BN;
    const int z  = blockIdx.z;

    const float* in   = (z ? inR : inC) + base;
    const float* Wt   =  z ? Wr : Wc;
    const float* bias =  z ? br : bc;
    const int    m0   = blockIdx.y * BMv;

    const int tid = threadIdx.x;
    const int tx = tid & 15, ty = tid >> 4;
    const int lane16 = tid & 15;
    const int kr     = tid >> 4;
    const int mcolA  = lane16 * MI;

    __shared__ float As[3][BK][BMv];
    __shared__ float Bs[3][BK][BN];

    float acc[MI][8];
#pragma unroll
    for (int i = 0; i < MI; i++)
#pragma unroll
        for (int j = 0; j < 8; j++) acc[i][j] = 0.f;

    int py[8], px[8];
#pragma unroll
    for (int j = 0; j < 8; j++) {
        int p = n0 + lane16 + j * 16;
        if (p < P) { py[j] = p / H; px[j] = p - py[j] * H; }
        else       { py[j] = -100000; px[j] = -100000; }
    }

    auto issue_tile = [&](int ktp, int buf) {
        const float* srcA = Wt + (size_t)(ktp * BK + kr) * MST + m0 + mcolA;
        unsigned dA = (unsigned)__cvta_generic_to_shared(&As[buf][kr][mcolA]);
#pragma unroll
        for (int q = 0; q < MI / 4; q++)
            asm volatile("cp.async.cg.shared.global [%0],[%1],16;\n"
                         :: "r"(dA + q * 16), "l"(srcA + q * 4));
        const int rs = ktp >> 4;
        const int c  = ((ktp & 15) << 4) + kr;
        const int dy = rs / 3 - 1, dx = rs - 3 * (rs / 3) - 1;
        const float* cptr = in + (size_t)c * P;
#pragma unroll
        for (int j = 0; j < 8; j++) {
            int iy = py[j] + dy, ix = px[j] + dx;
            bool ok = (iy >= 0) && (iy < H) && (ix >= 0) && (ix < H);
            const float* s = cptr + (ok ? (iy * H + ix) : 0);
            unsigned dB = (unsigned)__cvta_generic_to_shared(&Bs[buf][kr][lane16 + j * 16]);
            int zf = ok ? 4 : 0;
            asm volatile("cp.async.ca.shared.global [%0],[%1],4,%2;\n"
                         :: "r"(dB), "l"(s), "r"(zf));
        }
        asm volatile("cp.async.commit_group;\n");
    };

    issue_tile(0, 0);
    issue_tile(1, 1);

    int cur = 0;
    for (int kt = 0; kt < NT; kt++) {
        asm volatile("cp.async.wait_group 1;\n");
        __syncthreads();

#pragma unroll
        for (int kk = 0; kk < BK; kk++) {
            float a[MI], b[8];
#pragma unroll
            for (int q = 0; q < MI / 4; q++)
                *(float4*)&a[4 * q] = *(const float4*)&As[cur][kk][ty * MI + 4 * q];
            *(float4*)&b[0] = *(const float4*)&Bs[cur][kk][tx * 8];
            *(float4*)&b[4] = *(const float4*)&Bs[cur][kk][tx * 8 + 4];
#pragma unroll
            for (int i = 0; i < MI; i++)
#pragma unroll
                for (int j = 0; j < 8; j++)
                    acc[i][j] = __fmaf_rn(a[i], b[j], acc[i][j]);
        }

        if (kt + 2 < NT) {
            int ib = cur + 2; if (ib >= 3) ib -= 3;
            issue_tile(kt + 2, ib);
        } else {
            asm volatile("cp.async.commit_group;\n");
        }
        cur = (cur == 2) ? 0 : cur + 1;
    }

    float* out = (z ? outR : outC) + base;
#pragma unroll
    for (int i = 0; i < MI; i++) {
        const int m = m0 + ty * MI + i;
        const float bsum = bias[m];
#pragma unroll
        for (int j = 0; j < 8; j++) {
            int p = n0 + tx * 8 + j;
            if (p < P) out[(size_t)m * P + p] = fmaxf(__fadd_rn(acc[i][j], bsum), 0.f);
        }
    }
}

// ---------------- fused out-conv: both heads, BN=64, M=64 [cls|pad|reg] ----------------
// Each output's serial FMA chain (kt, kk ascending) identical to before — DO NOT REORDER.
__global__ __launch_bounds__(256, 2)
void conv_out(const float* __restrict__ inCf, const float* __restrict__ inRf,
              const float* __restrict__ cls_ob, const float* __restrict__ reg_ob)
{
    constexpr int BN = 64;

    const int bx = blockIdx.x;
    int l, ts;
    if      (bx < 100) { l = 0; ts = 0;   }
    else if (bx < 125) { l = 1; ts = 100; }
    else if (bx < 132) { l = 2; ts = 125; }
    else if (bx < 134) { l = 3; ts = 132; }
    else               { l = 4; ts = 134; }
    const int H = c_H[l];
    const int P = H * H;
    const int base = c_Pb[l];
    const int n0 = (bx - ts) * BN;

    const float* inC = inCf + base;
    const float* inR = inRf + base;

    const int tid = threadIdx.x;
    const int tx = tid & 15, ty = tid >> 4;
    const int lane16 = tid & 15;
    const int kr     = tid >> 4;

    __shared__ float As[3][BK][64];
    __shared__ float BsC[3][BK][BN];
    __shared__ float BsR[3][BK][BN];

    float acc[4][4];
#pragma unroll
    for (int i = 0; i < 4; i++)
#pragma unroll
        for (int j = 0; j < 4; j++) acc[i][j] = 0.f;

    int py[4], px[4];
#pragma unroll
    for (int j = 0; j < 4; j++) {
        int p = n0 + lane16 + j * 16;
        if (p < P) { py[j] = p / H; px[j] = p - py[j] * H; }
        else       { py[j] = -100000; px[j] = -100000; }
    }

    auto issue_tile = [&](int ktp, int buf) {
        const float* srcA = g_wo + (size_t)(ktp * BK + kr) * 64 + lane16 * 4;
        unsigned dA = (unsigned)__cvta_generic_to_shared(&As[buf][kr][lane16 * 4]);
        asm volatile("cp.async.cg.shared.global [%0],[%1],16;\n" :: "r"(dA), "l"(srcA));
        const int rs = ktp >> 4;
        const int c  = ((ktp & 15) << 4) + kr;
        const int dy = rs / 3 - 1, dx = rs - 3 * (rs / 3) - 1;
        const float* cptrC = inC + (size_t)c * P;
        const float* cptrR = inR + (size_t)c * P;
#pragma unroll
        for (int j = 0; j < 4; j++) {
            int iy = py[j] + dy, ix = px[j] + dx;
            bool ok = (iy >= 0) && (iy < H) && (ix >= 0) && (ix < H);
            int off = ok ? (iy * H + ix) : 0;
            int zf = ok ? 4 : 0;
            unsigned dC = (unsigned)__cvta_generic_to_shared(&BsC[buf][kr][lane16 + j * 16]);
            asm volatile("cp.async.ca.shared.global [%0],[%1],4,%2;\n"
                         :: "r"(dC), "l"(cptrC + off), "r"(zf));
            unsigned dR = (unsigned)__cvta_generic_to_shared(&BsR[buf][kr][lane16 + j * 16]);
            asm volatile("cp.async.ca.shared.global [%0],[%1],4,%2;\n"
                         :: "r"(dR), "l"(cptrR + off), "r"(zf));
        }
        asm volatile("cp.async.commit_group;\n");
    };

    issue_tile(0, 0);
    issue_tile(1, 1);

    const bool isCls = (ty < 4);

    int cur = 0;
    for (int kt = 0; kt < NT; kt++) {
        asm volatile("cp.async.wait_group 1;\n");
        __syncthreads();

#pragma unroll
        for (int kk = 0; kk < BK; kk++) {
            float a[4], b[4];
            *(float4*)&a[0] = *(const float4*)&As[cur][kk][ty * 4];
            if (isCls) *(float4*)&b[0] = *(const float4*)&BsC[cur][kk][tx * 4];
            else       *(float4*)&b[0] = *(const float4*)&BsR[cur][kk][tx * 4];
#pragma unroll
            for (int i = 0; i < 4; i++)
#pragma unroll
                for (int j = 0; j < 4; j++)
                    acc[i][j] = __fmaf_rn(a[i], b[j], acc[i][j]);
        }

        if (kt + 2 < NT) {
            int ib = cur + 2; if (ib >= 3) ib -= 3;
            issue_tile(kt + 2, ib);
        } else {
            asm volatile("cp.async.commit_group;\n");
        }
        cur = (cur == 2) ? 0 : cur + 1;
    }

    // ---------------- epilogues (bit-identical math) ----------------
    const int aoff = c_ao[l];
    if (isCls) {   // rows m = ty*4+i, real for m<9: sigmoid via double
#pragma unroll
        for (int i = 0; i < 4; i++) {
            const int m = ty * 4 + i;
            if (m < 9) {
                const float bsum = cls_ob[m];
#pragma unroll
                for (int j = 0; j < 4; j++) {
                    int p = n0 + tx * 4 + j;
                    if (p < P) {
                        float logit = __fadd_rn(acc[i][j], bsum);
                        double s = 1.0 / (1.0 + exp(-(double)logit));
                        g_scores[aoff + p * 9 + m] = (float)s;
                    }
                }
            }
        }
    } else {       // rows m = ty*4 (..+3), reg rows mm = m-16 in [0,36)
        const int mm = ty * 4 - 16;
        if (mm + 3 < 36) {
            const int a = mm >> 2;
            const int stride = c_str[l];
            const int ri = a / 3, si = a - 3 * ri;
            const double ratio = (ri == 0) ? 0.5 : ((ri == 1) ? 1.0 : 2.0);
            const double scl   = (si == 0) ? 1.0 : exp2((double)si / 3.0);
            const double bsz   = (double)(stride * 4) * scl;
            const double wA    = sqrt((bsz * bsz) / ratio);
            const double hA    = wA * ratio;
            const float b0v = reg_ob[mm + 0], b1v = reg_ob[mm + 1];
            const float b2v = reg_ob[mm + 2], b3v = reg_ob[mm + 3];
#pragma unroll
            for (int j = 0; j < 4; j++) {
                int p = n0 + tx * 4 + j;
                if (p < P) {
                    int yy = p / H;
                    int xx = p - yy * H;
                    double cxd = ((double)xx + 0.5) * (double)stride;
                    double cyd = ((double)yy + 0.5) * (double)stride;
                    float ax1 = (float)(cxd - 0.5 * wA);
                    float ay1 = (float)(cyd - 0.5 * hA);
                    float ax2 = (float)(cxd + 0.5 * wA);
                    float ay2 = (float)(cyd + 0.5 * hA);
                    float aw = __fsub_rn(ax2, ax1), ah = __fsub_rn(ay2, ay1);
                    float acx = __fadd_rn(ax1, 0.5f * aw);
                    float acy = __fadd_rn(ay1, 0.5f * ah);
                    float t0 = __fadd_rn(acc[0][j], b0v);
                    float t1 = __fadd_rn(acc[1][j], b1v);
                    float t2 = __fadd_rn(acc[2][j], b2v);
                    float t3 = __fadd_rn(acc[3][j], b3v);
                    float pcx = __fadd_rn(acx, __fmul_rn(__fmul_rn(t0, 0.1f), aw));
                    float pcy = __fadd_rn(acy, __fmul_rn(__fmul_rn(t1, 0.1f), ah));
                    float pw  = __fmul_rn((float)exp((double)__fmul_rn(t2, 0.2f)), aw);
                    float ph  = __fmul_rn((float)exp((double)__fmul_rn(t3, 0.2f)), ah);
                    float x1 = __fsub_rn(pcx, 0.5f * pw), y1 = __fsub_rn(pcy, 0.5f * ph);
                    float x2 = __fadd_rn(pcx, 0.5f * pw), y2 = __fadd_rn(pcy, 0.5f * ph);
                    x1 = fminf(fmaxf(x1, 0.f), 640.f);
                    y1 = fminf(fmaxf(y1, 0.f), 640.f);
                    x2 = fminf(fmaxf(x2, 0.f), 640.f);
                    y2 = fminf(fmaxf(y2, 0.f), 640.f);
                    g_boxes[aoff + p * 9 + a] = make_float4(x1, y1, x2, y2);
                }
            }
        }
    }
}

// ---------------- sort-based single-block NMS ----------------
__device__ __forceinline__ float iou_ref(float ax1, float ay1, float ax2, float ay2, float aar,
                                         float bx1, float by1, float bx2, float by2, float bar)
{
    float xx1 = fmaxf(ax1, bx1), yy1 = fmaxf(ay1, by1);
    float xx2 = fminf(ax2, bx2), yy2 = fminf(ay2, by2);
    float inter = __fmul_rn(fmaxf(__fsub_rn(xx2, xx1), 0.f),
                            fmaxf(__fsub_rn(yy2, yy1), 0.f));
    float denom = __fadd_rn(__fsub_rn(__fadd_rn(bar, aar), inter), 1e-8f);
    return __fdiv_rn(inter, denom);
}

__global__ __launch_bounds__(1024)
void nms_kernel(float* __restrict__ out)
{
    const int T = 1024;
    const int tid = threadIdx.x;

    extern __shared__ unsigned long long nms_smem[];
    unsigned long long* s_keys = nms_smem;                      // NMSCAP * 8B
    float4*             s_box  = (float4*)(nms_smem + NMSCAP);  // NMSCAP * 16B

    __shared__ int   s_hist[4096];
    __shared__ int   s_B, s_below, s_cnt, s_np, s_fp, s_fb;
    __shared__ float p_x1[MAXDET], p_y1[MAXDET], p_x2[MAXDET], p_y2[MAXDET];
    __shared__ float p_ar[MAXDET], p_sc[MAXDET];
    __shared__ int   s_mask[32];
    __shared__ float s_wv[32];
    __shared__ int   s_wi[32];

    for (int i = tid; i < 4096; i += T) s_hist[i] = 0;
    if (tid == 0) { s_cnt = 0; s_np = 0; }
    __syncthreads();

    for (int i = tid; i < NANCH; i += T) {
        float s = g_scores[i];
        if (s > 0.05f) atomicAdd(&s_hist[__float_as_uint(s) >> 18], 1);
    }
    __syncthreads();

    if (tid == 0) {
        int accum = 0, Bv = 0, below = 0;
        for (int b = 4095; b >= 0; b--) {
            int h = s_hist[b];
            if (Bv == 0) {
                if (accum + h > NMSCAP) { Bv = b + 1; below += h; }
                else accum += h;
            } else below += h;
        }
        s_B = Bv; s_below = below;
    }
    __syncthreads();
    const unsigned Bbin = (unsigned)s_B;

    for (int i = tid; i < NANCH; i += T) {
        float s = g_scores[i];
        if (s > 0.05f) {
            unsigned bits = __float_as_uint(s);
            if ((bits >> 18) >= Bbin) {
                int pos = atomicAdd(&s_cnt, 1);
                if (pos < NMSCAP)
                    s_keys[pos] = ((unsigned long long)bits << 32) | (unsigned)(~i);
            }
        }
    }
    __syncthreads();
    const int nsel = (s_cnt < NMSCAP) ? s_cnt : NMSCAP;

    if (nsel > 0) {
        int N2 = 1; while (N2 < nsel) N2 <<= 1;
        for (int i = nsel + tid; i < N2; i += T) s_keys[i] = 0ull;
        __syncthreads();

        for (int k2 = 2; k2 <= N2; k2 <<= 1) {
            for (int j = k2 >> 1; j > 0; j >>= 1) {
                for (int i = tid; i < N2; i += T) {
                    int p = i ^ j;
                    if (p > i) {
                        unsigned long long a = s_keys[i], b = s_keys[p];
                        bool dir = ((i & k2) == 0);
                        if ((a < b) == dir) { s_keys[i] = b; s_keys[p] = a; }
                    }
                }
                __syncthreads();
            }
        }

        for (int r = tid; r < nsel; r += T) {
            int idx = (int)(~(unsigned)(s_keys[r] & 0xffffffffu));
            s_box[r] = g_boxes[idx];
        }
        __syncthreads();

        for (int cur0 = 0; cur0 < nsel && s_np < MAXDET; cur0 += T) {
            int r = cur0 + tid;
            bool alive = (r < nsel);
            float4 bb = make_float4(0.f, 0.f, 0.f, 0.f);
            float ba = 0.f;
            if (alive) {
                bb = s_box[r];
                ba = __fmul_rn(__fsub_rn(bb.z, bb.x), __fsub_rn(bb.w, bb.y));
                int npc = s_np;
                for (int q = 0; q < npc; q++) {
                    float iou = iou_ref(p_x1[q], p_y1[q], p_x2[q], p_y2[q], p_ar[q],
                                        bb.x, bb.y, bb.z, bb.w, ba);
                    if (iou > 0.5f) { alive = false; break; }
                }
            }
            unsigned m = __ballot_sync(0xffffffffu, alive);
            if ((tid & 31) == 0) s_mask[tid >> 5] = (int)m;
            __syncthreads();

            while (true) {
                if (tid == 0) {
                    int fp = -1;
                    if (s_np < MAXDET) {
                        for (int wq = 0; wq < 32; wq++) {
                            unsigned mm = (unsigned)s_mask[wq];
                            if (mm) { fp = wq * 32 + __ffs(mm) - 1; break; }
                        }
                    }
                    s_fp = fp;
                }
                __syncthreads();
                int fp = s_fp;
                if (fp < 0) break;

                float4 pbb = s_box[cur0 + fp];
                float pba = __fmul_rn(__fsub_rn(pbb.z, pbb.x), __fsub_rn(pbb.w, pbb.y));
                if (tid == 0) {
                    int q = s_np;
                    p_x1[q] = pbb.x; p_y1[q] = pbb.y; p_x2[q] = pbb.z; p_y2[q] = pbb.w;
                    p_ar[q] = pba;
                    p_sc[q] = __uint_as_float((unsigned)(s_keys[cur0 + fp] >> 32));
                    s_np = q + 1;
                }
                if (alive) {
                    if (tid == fp) alive = false;
                    else {
                        float iou = iou_ref(pbb.x, pbb.y, pbb.z, pbb.w, pba,
                                            bb.x, bb.y, bb.z, bb.w, ba);
                        if (iou > 0.5f) alive = false;
                    }
                }
                unsigned m2 = __ballot_sync(0xffffffffu, alive);
                if ((tid & 31) == 0) s_mask[tid >> 5] = (int)m2;
                __syncthreads();
            }
            __syncthreads();
        }
    }

    if (tid == 0) s_fb = (s_np < MAXDET && s_below > 0) ? 1 : 0;
    __syncthreads();
    if (s_fb) {
        int npc = s_np;
        for (int i = tid; i < NANCH; i += T) {
            float s = g_scores[i];
            float v = -INFINITY;
            if (s > 0.05f && (__float_as_uint(s) >> 18) < Bbin) {
                float4 b = g_boxes[i];
                float ar = __fmul_rn(__fsub_rn(b.z, b.x), __fsub_rn(b.w, b.y));
                bool ok = true;
                for (int q = 0; q < npc; q++) {
                    float iou = iou_ref(p_x1[q], p_y1[q], p_x2[q], p_y2[q], p_ar[q],
                                        b.x, b.y, b.z, b.w, ar);
                    if (iou > 0.5f) { ok = false; break; }
                }
                if (ok) v = s;
                g_cb[i] = b; g_carea[i] = ar;
            }
            g_cs[i] = v;
        }
        __syncthreads();

        const int lane = tid & 31, w = tid >> 5;
        while (s_np < MAXDET) {
            float bv = -INFINITY; int bi = 0x7fffffff;
            for (int idx = tid; idx < NANCH; idx += T) {
                float v = g_cs[idx];
                if (v > bv || (v == bv && idx < bi)) { bv = v; bi = idx; }
            }
#pragma unroll
            for (int off = 16; off; off >>= 1) {
                float v2 = __shfl_down_sync(0xffffffffu, bv, off);
                int   i2 = __shfl_down_sync(0xffffffffu, bi, off);
                if (v2 > bv || (v2 == bv && i2 < bi)) { bv = v2; bi = i2; }
            }
            if (lane == 0) { s_wv[w] = bv; s_wi[w] = bi; }
            __syncthreads();
            if (w == 0) {
                bv = s_wv[lane]; bi = s_wi[lane];
#pragma unroll
                for (int off = 16; off; off >>= 1) {
                    float v2 = __shfl_down_sync(0xffffffffu, bv, off);
                    int   i2 = __shfl_down_sync(0xffffffffu, bi, off);
                    if (v2 > bv || (v2 == bv && i2 < bi)) { bv = v2; bi = i2; }
                }
                if (lane == 0) { s_wv[0] = bv; s_wi[0] = bi; }
            }
            __syncthreads();
            float sj = s_wv[0];
            int   j  = s_wi[0];
            if (!(sj > -INFINITY)) break;
            float4 pb = g_cb[j];
            float pba = g_carea[j];
            if (tid == 0) {
                int q = s_np;
                p_x1[q] = pb.x; p_y1[q] = pb.y; p_x2[q] = pb.z; p_y2[q] = pb.w;
                p_ar[q] = pba; p_sc[q] = sj;
                s_np = q + 1;
            }
            for (int idx = tid; idx < NANCH; idx += T) {
                float v = g_cs[idx];
                if (v == -INFINITY) continue;
                float4 b = g_cb[idx];
                float iou = iou_ref(pb.x, pb.y, pb.z, pb.w, pba,
                                    b.x, b.y, b.z, b.w, g_carea[idx]);
                if (iou > 0.5f) g_cs[idx] = -INFINITY;
            }
            __syncthreads();
        }
    }
    __syncthreads();

    const int np = s_np;
    for (int i = tid; i < MAXDET; i += T) {
        bool sel = (i < np);
        float s = sel ? p_sc[i] : 0.f;
        out[i] = s;
        out[MAXDET + i] = (s > 0.f) ? 0.f : -1.f;
        out[2 * MAXDET + 4 * i + 0] = sel ? p_x1[i] : 0.f;
        out[2 * MAXDET + 4 * i + 1] = sel ? p_y1[i] : 0.f;
        out[2 * MAXDET + 4 * i + 2] = sel ? p_x2[i] : 0.f;
        out[2 * MAXDET + 4 * i + 3] = sel ? p_y2[i] : 0.f;
    }
}

// ---------------- host launcher ----------------
extern "C" void kernel_launch(void* const* d_in, const int* in_sizes, int n_in,
                              void* d_out, int out_size)
{
    const float* feats[5] = {
        (const float*)d_in[1], (const float*)d_in[2], (const float*)d_in[3],
        (const float*)d_in[4], (const float*)d_in[5]
    };
    const float* cls_w  = (const float*)d_in[6];
    const float* cls_b  = (const float*)d_in[7];
    const float* cls_ow = (const float*)d_in[8];
    const float* cls_ob = (const float*)d_in[9];
    const float* reg_w  = (const float*)d_in[10];
    const float* reg_b  = (const float*)d_in[11];
    const float* reg_ow = (const float*)d_in[12];
    const float* reg_ob = (const float*)d_in[13];

    float *feat, *hA0, *hA1, *hB0, *hB1, *wc, *wr;
    cudaGetSymbolAddress((void**)&feat, g_feat);
    cudaGetSymbolAddress((void**)&hA0, g_hA0);
    cudaGetSymbolAddress((void**)&hA1, g_hA1);
    cudaGetSymbolAddress((void**)&hB0, g_hB0);
    cudaGetSymbolAddress((void**)&hB1, g_hB1);
    cudaGetSymbolAddress((void**)&wc, g_wc);
    cudaGetSymbolAddress((void**)&wr, g_wr);

    // transpose weights to [k][m] layout (+ combined out weights)
    const int ttot = HID_TOT + OUT_ELEM;
    transpose_w<<<(ttot + 255) / 256, 256>>>(cls_w, reg_w, cls_ow, reg_ow);

    // gather feature pyramid into one packed buffer
    const size_t foff[5] = {0, 1638400, 2048000, 2150400, 2176000};
    const size_t fsz[5]  = {1638400, 409600, 102400, 25600, 6400};
    for (int l = 0; l < 5; l++)
        cudaMemcpyAsync(feat + foff[l], feats[l], fsz[l] * sizeof(float),
                        cudaMemcpyDeviceToDevice);

    const size_t LW = (size_t)HID_ELEM;
    dim3 gh(69, 2, 2);   // hidden: BM=128, 2 M-tiles, 2 heads

    conv_hidden<<<gh, 256>>>(feat, feat, wc + 0 * LW, wr + 0 * LW,
                             cls_b + 0,   reg_b + 0,   hA0, hB0);
    conv_hidden<<<gh, 256>>>(hA0,  hB0,  wc + 1 * LW, wr + 1 * LW,
                             cls_b + 256, reg_b + 256, hA1, hB1);
    conv_hidden<<<gh, 256>>>(hA1,  hB1,  wc + 2 * LW, wr + 2 * LW,
                             cls_b + 512, reg_b + 512, hA0, hB0);
    conv_hidden<<<gh, 256>>>(hA0,  hB0,  wc + 3 * LW, wr + 3 * LW,
                             cls_b + 768, reg_b + 768, hA1, hB1);
    conv_out<<<135, 256>>>(hA1, hB1, cls_ob, reg_ob);

    const int NMS_DYN = NMSCAP * 8 + NMSCAP * 16;   // 196608 B
    cudaFuncSetAttribute(nms_kernel, cudaFuncAttributeMaxDynamicSharedMemorySize, NMS_DYN);
    nms_kernel<<<1, 1024, NMS_DYN>>>((float*)d_out);
}

// round 15
// speedup vs baseline: 1.1326x; 1.0097x over previous
#include <cuda_runtime.h>
#include <math.h>

#define KTOT  2304          // 9*256, k = (ky*3+kx)*256 + c  (chain order)
#define NANCH 76725
#define MAXDET 300
#define NMSCAP 8192

#define BK 16
#define NT  144             // KTOT/BK
#define BUFSZ (8525*256)

#define HID_ELEM (2304*256)       // per-layer weight elems
#define HID_TOT  (8*HID_ELEM)
#define OUT_ELEM (2304*64)        // combined out weights [k][64]

// ---------------- scratch (device globals; no allocation) ----------------
__device__ __align__(16) float  g_hA0[BUFSZ];
__device__ __align__(16) float  g_hA1[BUFSZ];
__device__ __align__(16) float  g_hB0[BUFSZ];
__device__ __align__(16) float  g_hB1[BUFSZ];
__device__ __align__(16) float  g_wc[4 * HID_ELEM];   // cls hidden, [layer][k][m=256]
__device__ __align__(16) float  g_wr[4 * HID_ELEM];   // reg hidden, [layer][k][m=256]
__device__ __align__(16) float  g_wo[OUT_ELEM];       // out, [k][64]: 0-8 cls, 16-51 reg, rest 0
__device__ float  g_scores[NANCH];
__device__ float4 g_boxes[NANCH];
__device__ float  g_cs[NANCH];     // fallback only
__device__ float4 g_cb[NANCH];
__device__ float  g_carea[NANCH];

// per-level tables
__constant__ int c_H[5]   = {80, 40, 20, 10, 5};
__constant__ int c_Pb[5]  = {0, 1638400, 2048000, 2150400, 2176000};
__constant__ int c_str[5] = {8, 16, 32, 64, 128};
__constant__ int c_ao[5]  = {0, 57600, 72000, 75600, 76500};

// ---------------- weight transpose: OIHW (m, c*9+rs) -> [k][m], k = rs*256+c ----
// blocks 0-511: hidden weights, tiled+coalesced through smem
// blocks 512-1087: combined out weights, scatter (small)
__global__ void transpose_w(const float* __restrict__ cw, const float* __restrict__ rw,
                            const float* __restrict__ cow, const float* __restrict__ row_)
{
    const int b = blockIdx.x, tid = threadIdx.x;
    if (b < 512) {
        __shared__ float sm[32][289];
        const int sub = b >> 6;                 // head*4 + layer
        const int t = b & 63;
        const int head = sub >> 2, layer = sub & 3;
        const int m0 = (t >> 3) * 32, c0 = (t & 7) * 32;
        const float* src = (head ? rw : cw) + (size_t)layer * HID_ELEM;
        float*       dst = (head ? g_wr : g_wc) + (size_t)layer * HID_ELEM;
        const int i = tid >> 3, ln = tid & 7;
        const float* srow = src + (size_t)(m0 + i) * KTOT + c0 * 9;
#pragma unroll
        for (int w = 0; w < 36; w++) {
            int cc = w * 8 + ln;
            sm[i][cc] = srow[cc];
        }
        __syncthreads();
#pragma unroll
        for (int w = 0; w < 36; w++) {
            int flat = w * 256 + tid;
            int kk = flat >> 5, ii = flat & 31;
            int rs = kk >> 5, j = kk & 31;
            dst[(size_t)(rs * 256 + c0 + j) * 256 + m0 + ii] = sm[ii][j * 9 + rs];
        }
    } else {
        const int r2 = (b - 512) * 256 + tid;
        if (r2 >= OUT_ELEM) return;
        const int k = r2 >> 6, col = r2 & 63;
        const int c = k & 255, rs = k >> 8;
        float v = 0.f;
        if (col < 9)                      v = cow[(size_t)col * KTOT + c * 9 + rs];
        else if (col >= 16 && col < 52)   v = row_[(size_t)(col - 16) * KTOT + c * 9 + rs];
        g_wo[r2] = v;
    }
}

// ---------------- hidden implicit-GEMM conv, 3-stage cp.async pipeline ----------------
// Serial FMA chain per output (kt, kk ascending, single accumulator) — DO NOT REORDER.
// FIRST=1: layer-1, reads the original per-level feature pointers directly.
template <int FIRST>
__global__ __launch_bounds__(256, 2)
void conv_hidden(const float* __restrict__ inC, const float* __restrict__ inR,
                 const float* __restrict__ f0, const float* __restrict__ f1,
                 const float* __restrict__ f2, const float* __restrict__ f3,
                 const float* __restrict__ f4,
                 const float* __restrict__ Wc,  const float* __restrict__ Wr,
                 const float* __restrict__ bc,  const float* __restrict__ br,
                 float* outC, float* outR)
{
    constexpr int MI = 8;
    constexpr int BMv = 128;
    constexpr int BN = 128;
    constexpr int MST = 256;

    const int bx = blockIdx.x;
    int l, ts;
    if      (bx < 50) { l = 0; ts = 0;  }
    else if (bx < 63) { l = 1; ts = 50; }
    else if (bx < 67) { l = 2; ts = 63; }
    else if (bx < 68) { l = 3; ts = 67; }
    else              { l = 4; ts = 68; }
    const int H = c_H[l];
    const int P = H * H;
    const int base = c_Pb[l];
    const int n0 = (bx - ts) * BN;
    const int z  = blockIdx.z;

    const float* in;
    if (FIRST) {
        in = (l == 0) ? f0 : (l == 1) ? f1 : (l == 2) ? f2 : (l == 3) ? f3 : f4;
    } else {
        in = (z ? inR : inC) + base;
    }
    const float* Wt   =  z ? Wr : Wc;
    const float* bias =  z ? br : bc;
    const int    m0   = blockIdx.y * BMv;

    const int tid = threadIdx.x;
    const int tx = tid & 15, ty = tid >> 4;
    const int lane16 = tid & 15;
    const int kr     = tid >> 4;
    const int mcolA  = lane16 * MI;

    __shared__ float As[3][BK][BMv];
    __shared__ float Bs[3][BK][BN];

    float acc[MI][8];
#pragma unroll
    for (int i = 0; i < MI; i++)
#pragma unroll
        for (int j = 0; j < 8; j++) acc[i][j] = 0.f;

    int py[8], px[8];
#pragma unroll
    for (int j = 0; j < 8; j++) {
        int p = n0 + lane16 + j * 16;
        if (p < P) { py[j] = p / H; px[j] = p - py[j] * H; }
        else       { py[j] = -100000; px[j] = -100000; }
    }

    auto issue_tile = [&](int ktp, int buf) {
        const float* srcA = Wt + (size_t)(ktp * BK + kr) * MST + m0 + mcolA;
        unsigned dA = (unsigned)__cvta_generic_to_shared(&As[buf][kr][mcolA]);
#pragma unroll
        for (int q = 0; q < MI / 4; q++)
            asm volatile("cp.async.cg.shared.global [%0],[%1],16;\n"
                         :: "r"(dA + q * 16), "l"(srcA + q * 4));
        const int rs = ktp >> 4;
        const int c  = ((ktp & 15) << 4) + kr;
        const int dy = rs / 3 - 1, dx = rs - 3 * (rs / 3) - 1;
        const float* cptr = in + (size_t)c * P;
#pragma unroll
        for (int j = 0; j < 8; j++) {
            int iy = py[j] + dy, ix = px[j] + dx;
            bool ok = (iy >= 0) && (iy < H) && (ix >= 0) && (ix < H);
            const float* s = cptr + (ok ? (iy * H + ix) : 0);
            unsigned dB = (unsigned)__cvta_generic_to_shared(&Bs[buf][kr][lane16 + j * 16]);
            int zf = ok ? 4 : 0;
            asm volatile("cp.async.ca.shared.global [%0],[%1],4,%2;\n"
                         :: "r"(dB), "l"(s), "r"(zf));
        }
        asm volatile("cp.async.commit_group;\n");
    };

    issue_tile(0, 0);
    issue_tile(1, 1);

    int cur = 0;
    for (int kt = 0; kt < NT; kt++) {
        asm volatile("cp.async.wait_group 1;\n");
        __syncthreads();

#pragma unroll
        for (int kk = 0; kk < BK; kk++) {
            float a[MI], b[8];
#pragma unroll
            for (int q = 0; q < MI / 4; q++)
                *(float4*)&a[4 * q] = *(const float4*)&As[cur][kk][ty * MI + 4 * q];
            *(float4*)&b[0] = *(const float4*)&Bs[cur][kk][tx * 8];
            *(float4*)&b[4] = *(const float4*)&Bs[cur][kk][tx * 8 + 4];
#pragma unroll
            for (int i = 0; i < MI; i++)
#pragma unroll
                for (int j = 0; j < 8; j++)
                    acc[i][j] = __fmaf_rn(a[i], b[j], acc[i][j]);
        }

        if (kt + 2 < NT) {
            int ib = cur + 2; if (ib >= 3) ib -= 3;
            issue_tile(kt + 2, ib);
        } else {
            asm volatile("cp.async.commit_group;\n");
        }
        cur = (cur == 2) ? 0 : cur + 1;
    }

    float* out = (z ? outR : outC) + base;
#pragma unroll
    for (int i = 0; i < MI; i++) {
        const int m = m0 + ty * MI + i;
        const float bsum = bias[m];
#pragma unroll
        for (int j = 0; j < 8; j++) {
            int p = n0 + tx * 8 + j;
            if (p < P) out[(size_t)m * P + p] = fmaxf(__fadd_rn(acc[i][j], bsum), 0.f);
        }
    }
}

// ---------------- fused out-conv: both heads, BN=32, M=64 [cls|pad|reg] ----------------
// Each output's serial FMA chain (kt, kk ascending) identical to before — DO NOT REORDER.
__global__ __launch_bounds__(256, 2)
void conv_out(const float* __restrict__ inCf, const float* __restrict__ inRf,
              const float* __restrict__ cls_ob, const float* __restrict__ reg_ob)
{
    constexpr int BN = 32;

    const int bx = blockIdx.x;
    int l, ts;
    if      (bx < 200) { l = 0; ts = 0;   }
    else if (bx < 250) { l = 1; ts = 200; }
    else if (bx < 263) { l = 2; ts = 250; }
    else if (bx < 267) { l = 3; ts = 263; }
    else               { l = 4; ts = 267; }
    const int H = c_H[l];
    const int P = H * H;
    const int base = c_Pb[l];
    const int n0 = (bx - ts) * BN;

    const float* inC = inCf + base;
    const float* inR = inRf + base;

    const int tid = threadIdx.x;
    const int tx = tid & 15, ty = tid >> 4;
    const int lane16 = tid & 15;
    const int kr     = tid >> 4;

    __shared__ float As[3][BK][64];
    __shared__ float BsC[3][BK][BN];
    __shared__ float BsR[3][BK][BN];

    float acc[4][2];
#pragma unroll
    for (int i = 0; i < 4; i++)
#pragma unroll
        for (int j = 0; j < 2; j++) acc[i][j] = 0.f;

    int py[2], px[2];
#pragma unroll
    for (int j = 0; j < 2; j++) {
        int p = n0 + lane16 + j * 16;
        if (p < P) { py[j] = p / H; px[j] = p - py[j] * H; }
        else       { py[j] = -100000; px[j] = -100000; }
    }

    auto issue_tile = [&](int ktp, int buf) {
        const float* srcA = g_wo + (size_t)(ktp * BK + kr) * 64 + lane16 * 4;
        unsigned dA = (unsigned)__cvta_generic_to_shared(&As[buf][kr][lane16 * 4]);
        asm volatile("cp.async.cg.shared.global [%0],[%1],16;\n" :: "r"(dA), "l"(srcA));
        const int rs = ktp >> 4;
        const int c  = ((ktp & 15) << 4) + kr;
        const int dy = rs / 3 - 1, dx = rs - 3 * (rs / 3) - 1;
        const float* cptrC = inC + (size_t)c * P;
        const float* cptrR = inR + (size_t)c * P;
#pragma unroll
        for (int j = 0; j < 2; j++) {
            int iy = py[j] + dy, ix = px[j] + dx;
            bool ok = (iy >= 0) && (iy < H) && (ix >= 0) && (ix < H);
            int off = ok ? (iy * H + ix) : 0;
            int zf = ok ? 4 : 0;
            unsigned dC = (unsigned)__cvta_generic_to_shared(&BsC[buf][kr][lane16 + j * 16]);
            asm volatile("cp.async.ca.shared.global [%0],[%1],4,%2;\n"
                         :: "r"(dC), "l"(cptrC + off), "r"(zf));
            unsigned dR = (unsigned)__cvta_generic_to_shared(&BsR[buf][kr][lane16 + j * 16]);
            asm volatile("cp.async.ca.shared.global [%0],[%1],4,%2;\n"
                         :: "r"(dR), "l"(cptrR + off), "r"(zf));
        }
        asm volatile("cp.async.commit_group;\n");
    };

    issue_tile(0, 0);
    issue_tile(1, 1);

    const bool isCls = (ty < 4);

    int cur = 0;
    for (int kt = 0; kt < NT; kt++) {
        asm volatile("cp.async.wait_group 1;\n");
        __syncthreads();

#pragma unroll
        for (int kk = 0; kk < BK; kk++) {
            float a[4], b[2];
            *(float4*)&a[0] = *(const float4*)&As[cur][kk][ty * 4];
            if (isCls) *(float2*)&b[0] = *(const float2*)&BsC[cur][kk][tx * 2];
            else       *(float2*)&b[0] = *(const float2*)&BsR[cur][kk][tx * 2];
#pragma unroll
            for (int i = 0; i < 4; i++)
#pragma unroll
                for (int j = 0; j < 2; j++)
                    acc[i][j] = __fmaf_rn(a[i], b[j], acc[i][j]);
        }

        if (kt + 2 < NT) {
            int ib = cur + 2; if (ib >= 3) ib -= 3;
            issue_tile(kt + 2, ib);
        } else {
            asm volatile("cp.async.commit_group;\n");
        }
        cur = (cur == 2) ? 0 : cur + 1;
    }

    // ---------------- epilogues (bit-identical math) ----------------
    const int aoff = c_ao[l];
    if (isCls) {   // rows m = ty*4+i, real for m<9: sigmoid via double
#pragma unroll
        for (int i = 0; i < 4; i++) {
            const int m = ty * 4 + i;
            if (m < 9) {
                const float bsum = cls_ob[m];
#pragma unroll
                for (int j = 0; j < 2; j++) {
                    int p = n0 + tx * 2 + j;
                    if (p < P) {
                        float logit = __fadd_rn(acc[i][j], bsum);
                        double s = 1.0 / (1.0 + exp(-(double)logit));
                        g_scores[aoff + p * 9 + m] = (float)s;
                    }
                }
            }
        }
    } else {       // rows m = ty*4 (..+3), reg rows mm = m-16 in [0,36)
        const int mm = ty * 4 - 16;
        if (mm + 3 < 36) {
            const int a = mm >> 2;
            const int stride = c_str[l];
            const int ri = a / 3, si = a - 3 * ri;
            const double ratio = (ri == 0) ? 0.5 : ((ri == 1) ? 1.0 : 2.0);
            const double scl   = (si == 0) ? 1.0 : exp2((double)si / 3.0);
            const double bsz   = (double)(stride * 4) * scl;
            const double wA    = sqrt((bsz * bsz) / ratio);
            const double hA    = wA * ratio;
            const float b0v = reg_ob[mm + 0], b1v = reg_ob[mm + 1];
            const float b2v = reg_ob[mm + 2], b3v = reg_ob[mm + 3];
#pragma unroll
            for (int j = 0; j < 2; j++) {
                int p = n0 + tx * 2 + j;
                if (p < P) {
                    int yy = p / H;
                    int xx = p - yy * H;
                    double cxd = ((double)xx + 0.5) * (double)stride;
                    double cyd = ((double)yy + 0.5) * (double)stride;
                    float ax1 = (float)(cxd - 0.5 * wA);
                    float ay1 = (float)(cyd - 0.5 * hA);
                    float ax2 = (float)(cxd + 0.5 * wA);
                    float ay2 = (float)(cyd + 0.5 * hA);
                    float aw = __fsub_rn(ax2, ax1), ah = __fsub_rn(ay2, ay1);
                    float acx = __fadd_rn(ax1, 0.5f * aw);
                    float acy = __fadd_rn(ay1, 0.5f * ah);
                    float t0 = __fadd_rn(acc[0][j], b0v);
                    float t1 = __fadd_rn(acc[1][j], b1v);
                    float t2 = __fadd_rn(acc[2][j], b2v);
                    float t3 = __fadd_rn(acc[3][j], b3v);
                    float pcx = __fadd_rn(acx, __fmul_rn(__fmul_rn(t0, 0.1f), aw));
                    float pcy = __fadd_rn(acy, __fmul_rn(__fmul_rn(t1, 0.1f), ah));
                    float pw  = __fmul_rn((float)exp((double)__fmul_rn(t2, 0.2f)), aw);
                    float ph  = __fmul_rn((float)exp((double)__fmul_rn(t3, 0.2f)), ah);
                    float x1 = __fsub_rn(pcx, 0.5f * pw), y1 = __fsub_rn(pcy, 0.5f * ph);
                    float x2 = __fadd_rn(pcx, 0.5f * pw), y2 = __fadd_rn(pcy, 0.5f * ph);
                    x1 = fminf(fmaxf(x1, 0.f), 640.f);
                    y1 = fminf(fmaxf(y1, 0.f), 640.f);
                    x2 = fminf(fmaxf(x2, 0.f), 640.f);
                    y2 = fminf(fmaxf(y2, 0.f), 640.f);
                    g_boxes[aoff + p * 9 + a] = make_float4(x1, y1, x2, y2);
                }
            }
        }
    }
}

// ---------------- sort-based single-block NMS ----------------
__device__ __forceinline__ float iou_ref(float ax1, float ay1, float ax2, float ay2, float aar,
                                         float bx1, float by1, float bx2, float by2, float bar)
{
    float xx1 = fmaxf(ax1, bx1), yy1 = fmaxf(ay1, by1);
    float xx2 = fminf(ax2, bx2), yy2 = fminf(ay2, by2);
    float inter = __fmul_rn(fmaxf(__fsub_rn(xx2, xx1), 0.f),
                            fmaxf(__fsub_rn(yy2, yy1), 0.f));
    float denom = __fadd_rn(__fsub_rn(__fadd_rn(bar, aar), inter), 1e-8f);
    return __fdiv_rn(inter, denom);
}

__global__ __launch_bounds__(1024)
void nms_kernel(float* __restrict__ out)
{
    const int T = 1024;
    const int tid = threadIdx.x;

    extern __shared__ unsigned long long nms_smem[];
    unsigned long long* s_keys = nms_smem;                      // NMSCAP * 8B
    float4*             s_box  = (float4*)(nms_smem + NMSCAP);  // NMSCAP * 16B

    __shared__ int   s_hist[4096];
    __shared__ int   s_B, s_below, s_cnt, s_np, s_fp, s_fb;
    __shared__ float p_x1[MAXDET], p_y1[MAXDET], p_x2[MAXDET], p_y2[MAXDET];
    __shared__ float p_ar[MAXDET], p_sc[MAXDET];
    __shared__ int   s_mask[32];
    __shared__ float s_wv[32];
    __shared__ int   s_wi[32];

    for (int i = tid; i < 4096; i += T) s_hist[i] = 0;
    if (tid == 0) { s_cnt = 0; s_np = 0; }
    __syncthreads();

    for (int i = tid; i < NANCH; i += T) {
        float s = g_scores[i];
        if (s > 0.05f) atomicAdd(&s_hist[__float_as_uint(s) >> 18], 1);
    }
    __syncthreads();

    if (tid == 0) {
        int accum = 0, Bv = 0, below = 0;
        for (int b = 4095; b >= 0; b--) {
            int h = s_hist[b];
            if (Bv == 0) {
                if (accum + h > NMSCAP) { Bv = b + 1; below += h; }
                else accum += h;
            } else below += h;
        }
        s_B = Bv; s_below = below;
    }
    __syncthreads();
    const unsigned Bbin = (unsigned)s_B;

    for (int i = tid; i < NANCH; i += T) {
        float s = g_scores[i];
        if (s > 0.05f) {
            unsigned bits = __float_as_uint(s);
            if ((bits >> 18) >= Bbin) {
                int pos = atomicAdd(&s_cnt, 1);
                if (pos < NMSCAP)
                    s_keys[pos] = ((unsigned long long)bits << 32) | (unsigned)(~i);
            }
        }
    }
    __syncthreads();
    const int nsel = (s_cnt < NMSCAP) ? s_cnt : NMSCAP;

    if (nsel > 0) {
        int N2 = 1; while (N2 < nsel) N2 <<= 1;
        for (int i = nsel + tid; i < N2; i += T) s_keys[i] = 0ull;
        __syncthreads();

        for (int k2 = 2; k2 <= N2; k2 <<= 1) {
            for (int j = k2 >> 1; j > 0; j >>= 1) {
                for (int i = tid; i < N2; i += T) {
                    int p = i ^ j;
                    if (p > i) {
                        unsigned long long a = s_keys[i], b = s_keys[p];
                        bool dir = ((i & k2) == 0);
                        if ((a < b) == dir) { s_keys[i] = b; s_keys[p] = a; }
                    }
                }
                __syncthreads();
            }
        }

        for (int r = tid; r < nsel; r += T) {
            int idx = (int)(~(unsigned)(s_keys[r] & 0xffffffffu));
            s_box[r] = g_boxes[idx];
        }
        __syncthreads();

        for (int cur0 = 0; cur0 < nsel && s_np < MAXDET; cur0 += T) {
            int r = cur0 + tid;
            bool alive = (r < nsel);
            float4 bb = make_float4(0.f, 0.f, 0.f, 0.f);
            float ba = 0.f;
            if (alive) {
                bb = s_box[r];
                ba = __fmul_rn(__fsub_rn(bb.z, bb.x), __fsub_rn(bb.w, bb.y));
                int npc = s_np;
                for (int q = 0; q < npc; q++) {
                    float iou = iou_ref(p_x1[q], p_y1[q], p_x2[q], p_y2[q], p_ar[q],
                                        bb.x, bb.y, bb.z, bb.w, ba);
                    if (iou > 0.5f) { alive = false; break; }
                }
            }
            unsigned m = __ballot_sync(0xffffffffu, alive);
            if ((tid & 31) == 0) s_mask[tid >> 5] = (int)m;
            __syncthreads();

            while (true) {
                if (tid == 0) {
                    int fp = -1;
                    if (s_np < MAXDET) {
                        for (int wq = 0; wq < 32; wq++) {
                            unsigned mm = (unsigned)s_mask[wq];
                            if (mm) { fp = wq * 32 + __ffs(mm) - 1; break; }
                        }
                    }
                    s_fp = fp;
                }
                __syncthreads();
                int fp = s_fp;
                if (fp < 0) break;

                float4 pbb = s_box[cur0 + fp];
                float pba = __fmul_rn(__fsub_rn(pbb.z, pbb.x), __fsub_rn(pbb.w, pbb.y));
                if (tid == 0) {
                    int q = s_np;
                    p_x1[q] = pbb.x; p_y1[q] = pbb.y; p_x2[q] = pbb.z; p_y2[q] = pbb.w;
                    p_ar[q] = pba;
                    p_sc[q] = __uint_as_float((unsigned)(s_keys[cur0 + fp] >> 32));
                    s_np = q + 1;
                }
                if (alive) {
                    if (tid == fp) alive = false;
                    else {
                        float iou = iou_ref(pbb.x, pbb.y, pbb.z, pbb.w, pba,
                                            bb.x, bb.y, bb.z, bb.w, ba);
                        if (iou > 0.5f) alive = false;
                    }
                }
                unsigned m2 = __ballot_sync(0xffffffffu, alive);
                if ((tid & 31) == 0) s_mask[tid >> 5] = (int)m2;
                __syncthreads();
            }
            __syncthreads();
        }
    }

    if (tid == 0) s_fb = (s_np < MAXDET && s_below > 0) ? 1 : 0;
    __syncthreads();
    if (s_fb) {
        int npc = s_np;
        for (int i = tid; i < NANCH; i += T) {
            float s = g_scores[i];
            float v = -INFINITY;
            if (s > 0.05f && (__float_as_uint(s) >> 18) < Bbin) {
                float4 b = g_boxes[i];
                float ar = __fmul_rn(__fsub_rn(b.z, b.x), __fsub_rn(b.w, b.y));
                bool ok = true;
                for (int q = 0; q < npc; q++) {
                    float iou = iou_ref(p_x1[q], p_y1[q], p_x2[q], p_y2[q], p_ar[q],
                                        b.x, b.y, b.z, b.w, ar);
                    if (iou > 0.5f) { ok = false; break; }
                }
                if (ok) v = s;
                g_cb[i] = b; g_carea[i] = ar;
            }
            g_cs[i] = v;
        }
        __syncthreads();

        const int lane = tid & 31, w = tid >> 5;
        while (s_np < MAXDET) {
            float bv = -INFINITY; int bi = 0x7fffffff;
            for (int idx = tid; idx < NANCH; idx += T) {
                float v = g_cs[idx];
                if (v > bv || (v == bv && idx < bi)) { bv = v; bi = idx; }
            }
#pragma unroll
            for (int off = 16; off; off >>= 1) {
                float v2 = __shfl_down_sync(0xffffffffu, bv, off);
                int   i2 = __shfl_down_sync(0xffffffffu, bi, off);
                if (v2 > bv || (v2 == bv && i2 < bi)) { bv = v2; bi = i2; }
            }
            if (lane == 0) { s_wv[w] = bv; s_wi[w] = bi; }
            __syncthreads();
            if (w == 0) {
                bv = s_wv[lane]; bi = s_wi[lane];
#pragma unroll
                for (int off = 16; off; off >>= 1) {
                    float v2 = __shfl_down_sync(0xffffffffu, bv, off);
                    int   i2 = __shfl_down_sync(0xffffffffu, bi, off);
                    if (v2 > bv || (v2 == bv && i2 < bi)) { bv = v2; bi = i2; }
                }
                if (lane == 0) { s_wv[0] = bv; s_wi[0] = bi; }
            }
            __syncthreads();
            float sj = s_wv[0];
            int   j  = s_wi[0];
            if (!(sj > -INFINITY)) break;
            float4 pb = g_cb[j];
            float pba = g_carea[j];
            if (tid == 0) {
                int q = s_np;
                p_x1[q] = pb.x; p_y1[q] = pb.y; p_x2[q] = pb.z; p_y2[q] = pb.w;
                p_ar[q] = pba; p_sc[q] = sj;
                s_np = q + 1;
            }
            for (int idx = tid; idx < NANCH; idx += T) {
                float v = g_cs[idx];
                if (v == -INFINITY) continue;
                float4 b = g_cb[idx];
                float iou = iou_ref(pb.x, pb.y, pb.z, pb.w, pba,
                                    b.x, b.y, b.z, b.w, g_carea[idx]);
                if (iou > 0.5f) g_cs[idx] = -INFINITY;
            }
            __syncthreads();
        }
    }
    __syncthreads();

    const int np = s_np;
    for (int i = tid; i < MAXDET; i += T) {
        bool sel = (i < np);
        float s = sel ? p_sc[i] : 0.f;
        out[i] = s;
        out[MAXDET + i] = (s > 0.f) ? 0.f : -1.f;
        out[2 * MAXDET + 4 * i + 0] = sel ? p_x1[i] : 0.f;
        out[2 * MAXDET + 4 * i + 1] = sel ? p_y1[i] : 0.f;
        out[2 * MAXDET + 4 * i + 2] = sel ? p_x2[i] : 0.f;
        out[2 * MAXDET + 4 * i + 3] = sel ? p_y2[i] : 0.f;
    }
}

// ---------------- host launcher ----------------
extern "C" void kernel_launch(void* const* d_in, const int* in_sizes, int n_in,
                              void* d_out, int out_size)
{
    const float* f0 = (const float*)d_in[1];
    const float* f1 = (const float*)d_in[2];
    const float* f2 = (const float*)d_in[3];
    const float* f3 = (const float*)d_in[4];
    const float* f4 = (const float*)d_in[5];
    const float* cls_w  = (const float*)d_in[6];
    const float* cls_b  = (const float*)d_in[7];
    const float* cls_ow = (const float*)d_in[8];
    const float* cls_ob = (const float*)d_in[9];
    const float* reg_w  = (const float*)d_in[10];
    const float* reg_b  = (const float*)d_in[11];
    const float* reg_ow = (const float*)d_in[12];
    const float* reg_ob = (const float*)d_in[13];

    float *hA0, *hA1, *hB0, *hB1, *wc, *wr;
    cudaGetSymbolAddress((void**)&hA0, g_hA0);
    cudaGetSymbolAddress((void**)&hA1, g_hA1);
    cudaGetSymbolAddress((void**)&hB0, g_hB0);
    cudaGetSymbolAddress((void**)&hB1, g_hB1);
    cudaGetSymbolAddress((void**)&wc, g_wc);
    cudaGetSymbolAddress((void**)&wr, g_wr);

    // transpose weights to [k][m] layout (tiled hidden + scatter out)
    transpose_w<<<512 + (OUT_ELEM + 255) / 256, 256>>>(cls_w, reg_w, cls_ow, reg_ow);

    const size_t LW = (size_t)HID_ELEM;
    dim3 gh(69, 2, 2);   // hidden: BM=128, 2 M-tiles, 2 heads

    conv_hidden<1><<<gh, 256>>>(nullptr, nullptr, f0, f1, f2, f3, f4,
                                wc + 0 * LW, wr + 0 * LW,
                                cls_b + 0,   reg_b + 0,   hA0, hB0);
    conv_hidden<0><<<gh, 256>>>(hA0,  hB0,  f0, f1, f2, f3, f4,
                                wc + 1 * LW, wr + 1 * LW,
                                cls_b + 256, reg_b + 256, hA1, hB1);
    conv_hidden<0><<<gh, 256>>>(hA1,  hB1,  f0, f1, f2, f3, f4,
                                wc + 2 * LW, wr + 2 * LW,
                                cls_b + 512, reg_b + 512, hA0, hB0);
    conv_hidden<0><<<gh, 256>>>(hA0,  hB0,  f0, f1, f2, f3, f4,
                                wc + 3 * LW, wr + 3 * LW,
                                cls_b + 768, reg_b + 768, hA1, hB1);
    conv_out<<<268, 256>>>(hA1, hB1, cls_ob, reg_ob);

    const int NMS_DYN = NMSCAP * 8 + NMSCAP * 16;   // 196608 B
    cudaFuncSetAttribute(nms_kernel, cudaFuncAttributeMaxDynamicSharedMemorySize, NMS_DYN);
    nms_kernel<<<1, 1024, NMS_DYN>>>((float*)d_out);
}